// round 6
// baseline (speedup 1.0000x reference)
#include <cuda_runtime.h>

#define BB 64
#define SS 1024
#define DD 1024
#define VV 1024

// ---------------- scratch (no allocation allowed) ----------------
// zeroed-every-call region (one contiguous memset):
//   [0]      w2    (64K floats)
//   [64K]    w3    (64K)
//   [128K]   accv  (64K)
//   [192K]   gs    (64K)
//   [256K]   hpre  (128K) -> [64][2048] (ho_pre | hf_pre)
__device__ float g_zbuf[BB * SS * 4 + BB * 2048];
// non-zeroed scratch: wsum (64K), h (128K)
__device__ float g_buf[BB * SS + BB * 2048];

#define OFF_W2   0
#define OFF_W3   (BB * SS)
#define OFF_ACCV (BB * SS * 2)
#define OFF_GS   (BB * SS * 3)
#define OFF_HPRE (BB * SS * 4)

#define OFF_WSUM 0
#define OFF_H    (BB * SS)

#define ROWS 64            // s-rows per CTA per pass (grid = 16 x 64 = 1024 CTAs)

// ---- shared inner loop: ROWS rows x 1024 cols, 8-deep manual load batching -
__device__ __forceinline__ void matvec_body(
    const float* __restrict__ Mb, const float* xs, int t0, float* __restrict__ y)
{
    float a0 = 0.f, a1 = 0.f, a2 = 0.f, a3 = 0.f;
#pragma unroll 1
    for (int s = 0; s < ROWS; s += 8) {
        float4 m[8];
#pragma unroll
        for (int j = 0; j < 8; ++j)
            m[j] = *reinterpret_cast<const float4*>(Mb + (size_t)(s + j) * SS + t0);
#pragma unroll
        for (int j = 0; j < 8; ++j) {
            float x = xs[s + j];
            a0 += x * m[j].x; a1 += x * m[j].y;
            a2 += x * m[j].z; a3 += x * m[j].w;
        }
    }
    atomicAdd(y + 0, a0); atomicAdd(y + 1, a1);
    atomicAdd(y + 2, a2); atomicAdd(y + 3, a3);
}

// ---------------- step pass A: w2[b,:] += w1_chunk @ step[b] ----------------
// w1 computed on the fly from the q-row. grid = (16, 64), block = 256.
__global__ void __launch_bounds__(256) k_stepA(
    const float* __restrict__ step,
    const int* __restrict__ qidx, const float* __restrict__ qmask)
{
    __shared__ float xs[ROWS];
    const int b  = blockIdx.y;
    const int s0 = blockIdx.x * ROWS;
    const float* stepb = step + (size_t)b * SS * SS;

    if (threadIdx.x < ROWS) {
        int q = qidx[b];
        xs[threadIdx.x] = qmask[b] * __ldg(stepb + (size_t)q * SS + s0 + threadIdx.x);
    }
    __syncthreads();
    matvec_body(stepb + (size_t)s0 * SS, xs, threadIdx.x * 4,
                g_zbuf + OFF_W2 + b * SS + threadIdx.x * 4);
}

// ---------------- step pass B: w3[b,:] += w2_chunk @ step[b] ----------------
__global__ void __launch_bounds__(256) k_stepB(const float* __restrict__ step)
{
    __shared__ float xs[ROWS];
    const int b  = blockIdx.y;
    const int s0 = blockIdx.x * ROWS;

    if (threadIdx.x < ROWS)
        xs[threadIdx.x] = __ldcg(g_zbuf + OFF_W2 + b * SS + s0 + threadIdx.x);
    __syncthreads();
    matvec_body(step + (size_t)b * SS * SS + (size_t)s0 * SS, xs, threadIdx.x * 4,
                g_zbuf + OFF_W3 + b * SS + threadIdx.x * 4);
}

// ---------------- map pass: wsum on the fly; accv += wsum_chunk @ map -------
// grid = (16, 64). Each CTA owns (b, s-chunk) exclusively -> writes wsum once.
__global__ void __launch_bounds__(256) k_mapC(
    const float* __restrict__ map, const float* __restrict__ step,
    const int* __restrict__ qidx, const float* __restrict__ qmask)
{
    __shared__ float xs[ROWS];
    const int b  = blockIdx.y;
    const int s0 = blockIdx.x * ROWS;
    const int q = qidx[b];
    const float m = qmask[b];

    if (threadIdx.x < ROWS) {
        int s = s0 + threadIdx.x;
        float v = m * __ldg(step + ((size_t)b * SS + (size_t)q) * SS + s)
                + __ldcg(g_zbuf + OFF_W2 + b * SS + s)
                + __ldcg(g_zbuf + OFF_W3 + b * SS + s);
        if (s == q) v += m;
        xs[threadIdx.x] = v;
        g_buf[OFF_WSUM + b * SS + s] = v;   // consumed by symbol_bank GEMM
    }
    __syncthreads();
    matvec_body(map + (size_t)b * SS * SS + (size_t)s0 * SS, xs, threadIdx.x * 4,
                g_zbuf + OFF_ACCV + b * SS + threadIdx.x * 4);
}

// ---------------- split-K GEMM with z-paired operands ----------------
// C[64, 1024-per-z] += A[64,Ktot] @ W[Ktot,1024]  (atomic accumulate)
// grid = (16 n-blocks, KSPLIT, 2), block = 256. BM=64 BN=64 BK=16, 4x4/thread.
template <int KSPLIT>
__global__ void __launch_bounds__(256) k_gemm(
    const float* __restrict__ A0, const float* __restrict__ A1,
    const float* __restrict__ W0, const float* __restrict__ W1,
    float* __restrict__ C0, float* __restrict__ C1,
    int lda, int ldc, int Ktot)
{
    const float* A = blockIdx.z ? A1 : A0;
    const float* W = blockIdx.z ? W1 : W0;
    float*       C = blockIdx.z ? C1 : C0;

    const int n0 = blockIdx.x * 64;
    const int kchunk = Ktot / KSPLIT;
    const int k0 = blockIdx.y * kchunk;

    __shared__ float As[16][68];
    __shared__ float Ws[16][64];

    const int tid = threadIdx.x;
    const int tx = tid & 15;
    const int ty = tid >> 4;

    float acc[4][4] = {};

    const int lm = tid >> 2;
    const int lk = (tid & 3) * 4;
    const int wk = tid >> 4;
    const int wn = (tid & 15) * 4;

    for (int kt = k0; kt < k0 + kchunk; kt += 16) {
        float4 a = *reinterpret_cast<const float4*>(A + (size_t)lm * lda + kt + lk);
        As[lk + 0][lm] = a.x;
        As[lk + 1][lm] = a.y;
        As[lk + 2][lm] = a.z;
        As[lk + 3][lm] = a.w;
        *reinterpret_cast<float4*>(&Ws[wk][wn]) =
            *reinterpret_cast<const float4*>(W + (size_t)(kt + wk) * 1024 + n0 + wn);
        __syncthreads();
#pragma unroll
        for (int k = 0; k < 16; ++k) {
            float4 av = *reinterpret_cast<const float4*>(&As[k][ty * 4]);
            float4 bv = *reinterpret_cast<const float4*>(&Ws[k][tx * 4]);
            acc[0][0] += av.x * bv.x; acc[0][1] += av.x * bv.y;
            acc[0][2] += av.x * bv.z; acc[0][3] += av.x * bv.w;
            acc[1][0] += av.y * bv.x; acc[1][1] += av.y * bv.y;
            acc[1][2] += av.y * bv.z; acc[1][3] += av.y * bv.w;
            acc[2][0] += av.z * bv.x; acc[2][1] += av.z * bv.y;
            acc[2][2] += av.z * bv.z; acc[2][3] += av.z * bv.w;
            acc[3][0] += av.w * bv.x; acc[3][1] += av.w * bv.y;
            acc[3][2] += av.w * bv.z; acc[3][3] += av.w * bv.w;
        }
        __syncthreads();
    }

#pragma unroll
    for (int i = 0; i < 4; ++i) {
        int m = ty * 4 + i;
#pragma unroll
        for (int j = 0; j < 4; ++j) {
            int n = n0 + tx * 4 + j;
            atomicAdd(&C[(size_t)m * ldc + n], acc[i][j]);
        }
    }
}

// ---------------- gelu+bias epilogue on hpre -> h (float4) ----------------
__device__ __forceinline__ float gelu_tanh(float x) {
    float x3 = x * x * x;
    return 0.5f * x * (1.0f + tanhf(0.7978845608028654f * (x + 0.044715f * x3)));
}

__global__ void k_gelu(const float* __restrict__ bo1,
                       const float* __restrict__ bf1) {
    int i = blockIdx.x * blockDim.x + threadIdx.x;   // 0..32767 float4s
    int e0 = i * 4;
    int n = e0 & 2047;                               // float4 never straddles 1024
    const float* bp = (n < 1024) ? (bo1 + n) : (bf1 + n - 1024);
    float4 h = *reinterpret_cast<const float4*>(g_zbuf + OFF_HPRE + e0);
    float4 r;
    r.x = gelu_tanh(h.x + bp[0]);
    r.y = gelu_tanh(h.y + bp[1]);
    r.z = gelu_tanh(h.z + bp[2]);
    r.w = gelu_tanh(h.w + bp[3]);
    *reinterpret_cast<float4*>(g_buf + OFF_H + e0) = r;
}

// ---------------- out pre-init with final biases ----------------
__global__ void k_outinit(float* __restrict__ out,
                          const float* __restrict__ bo2,
                          const float* __restrict__ bf2) {
    int i = blockIdx.x * blockDim.x + threadIdx.x;   // 0..32767 float4s
    int e0 = i * 4;
    int n = e0 & 1023;
    const float* bp = (e0 < BB * VV) ? (bo2 + n) : (bf2 + n);
    *reinterpret_cast<float4*>(out + e0) = *reinterpret_cast<const float4*>(bp);
}

// ---------------- launch ----------------
extern "C" void kernel_launch(void* const* d_in, const int* in_sizes, int n_in,
                              void* d_out, int out_size) {
    const float* map_memory  = (const float*)d_in[0];
    const float* step_memory = (const float*)d_in[1];
    const int*   query_idx   = (const int*)  d_in[2];
    const float* query_mask  = (const float*)d_in[3];
    const float* symbol_bank = (const float*)d_in[4];
    const float* value_bank  = (const float*)d_in[5];
    const float* Wo1 = (const float*)d_in[6];
    const float* bo1 = (const float*)d_in[7];
    const float* Wo2 = (const float*)d_in[8];
    const float* bo2 = (const float*)d_in[9];
    const float* Wf1 = (const float*)d_in[10];
    const float* bf1 = (const float*)d_in[11];
    const float* Wf2 = (const float*)d_in[12];
    const float* bf2 = (const float*)d_in[13];
    float* out = (float*)d_out;

    float *zbuf, *buf;
    cudaGetSymbolAddress((void**)&zbuf, g_zbuf);
    cudaGetSymbolAddress((void**)&buf,  g_buf);

    float* pwsum = buf  + OFF_WSUM;
    float* ph    = buf  + OFF_H;
    float* paccv = zbuf + OFF_ACCV;
    float* pgs   = zbuf + OFF_GS;
    float* phpre = zbuf + OFF_HPRE;

    // zero all atomic-accumulation targets; pre-bias d_out
    cudaMemsetAsync(zbuf, 0, (BB * SS * 4 + BB * 2048) * sizeof(float));
    k_outinit<<<128, 256>>>(out, bo2, bf2);

    // walk: 1024-CTA passes (16 s-chunks x 64 batches), 8-deep load batching
    dim3 mg(SS / ROWS, BB);
    k_stepA<<<mg, 256>>>(step_memory, query_idx, query_mask);   // w2
    k_stepB<<<mg, 256>>>(step_memory);                          // w3
    k_mapC <<<mg, 256>>>(map_memory, step_memory, query_idx, query_mask); // wsum+accv

    // gs = wsum@symbol_bank + accv@value_bank   (z-paired, both into pgs)
    dim3 g1(16, 8, 2);
    k_gemm<8><<<g1, 256>>>(pwsum, paccv, symbol_bank, value_bank,
                           pgs, pgs, SS, DD, SS);
    // hpre = [gs@Wo1 | gs@Wf1]
    dim3 g2(16, 8, 2);
    k_gemm<8><<<g2, 256>>>(pgs, pgs, Wo1, Wf1,
                           phpre, phpre + 1024, DD, 2048, DD);
    // h = gelu(hpre + bias)
    k_gelu<<<128, 256>>>(bo1, bf1);
    // out += [ho@Wo2 | hf@Wf2]   (atomic onto pre-biased d_out)
    dim3 g3(16, 8, 2);
    k_gemm<8><<<g3, 256>>>(ph, ph + 1024, Wo2, Wf2,
                           out, out + BB * VV, 2048, 1024, DD);
}

// round 8
// speedup vs baseline: 1.0600x; 1.0600x over previous
#include <cuda_runtime.h>

#define BB 64
#define SS 1024
#define DD 1024
#define VV 1024

// ---------------- scratch (no allocation allowed) ----------------
// zeroed-every-call region (one contiguous memset):
//   [0]      w2    (64K floats)
//   [64K]    w3    (64K)
//   [128K]   accv  (64K)
//   [192K]   gs    (64K)
//   [256K]   hpre  (128K) -> [64][2048] (ho_pre | hf_pre)
__device__ float g_zbuf[BB * SS * 4 + BB * 2048];
// non-zeroed scratch: wsum (64K)
__device__ float g_buf[BB * SS];

#define OFF_W2   0
#define OFF_W3   (BB * SS)
#define OFF_ACCV (BB * SS * 2)
#define OFF_GS   (BB * SS * 3)
#define OFF_HPRE (BB * SS * 4)

#define OFF_WSUM 0

#define ROWS 128           // s-rows per CTA per pass (grid = 8 x 64 = 512 CTAs)

// ---- shared inner loop: ROWS rows x 1024 cols, 8-deep manual load batching -
__device__ __forceinline__ void matvec_body(
    const float* __restrict__ Mb, const float* xs, int t0, float* __restrict__ y)
{
    float a0 = 0.f, a1 = 0.f, a2 = 0.f, a3 = 0.f;
#pragma unroll 1
    for (int s = 0; s < ROWS; s += 8) {
        float4 m[8];
#pragma unroll
        for (int j = 0; j < 8; ++j)
            m[j] = __ldcs(reinterpret_cast<const float4*>(Mb + (size_t)(s + j) * SS + t0));
#pragma unroll
        for (int j = 0; j < 8; ++j) {
            float x = xs[s + j];
            a0 += x * m[j].x; a1 += x * m[j].y;
            a2 += x * m[j].z; a3 += x * m[j].w;
        }
    }
    atomicAdd(y + 0, a0); atomicAdd(y + 1, a1);
    atomicAdd(y + 2, a2); atomicAdd(y + 3, a3);
}

// ---------------- step pass A: w2[b,:] += w1_chunk @ step[b] ----------------
// w1 computed on the fly from the q-row. grid = (8, 64), block = 256.
__global__ void __launch_bounds__(256) k_stepA(
    const float* __restrict__ step,
    const int* __restrict__ qidx, const float* __restrict__ qmask)
{
    __shared__ float xs[ROWS];
    const int b  = blockIdx.y;
    const int s0 = blockIdx.x * ROWS;
    const float* stepb = step + (size_t)b * SS * SS;

    if (threadIdx.x < ROWS) {
        int q = qidx[b];
        xs[threadIdx.x] = qmask[b] * __ldg(stepb + (size_t)q * SS + s0 + threadIdx.x);
    }
    __syncthreads();
    matvec_body(stepb + (size_t)s0 * SS, xs, threadIdx.x * 4,
                g_zbuf + OFF_W2 + b * SS + threadIdx.x * 4);
}

// ---------------- step pass B: w3[b,:] += w2_chunk @ step[b] ----------------
__global__ void __launch_bounds__(256) k_stepB(const float* __restrict__ step)
{
    __shared__ float xs[ROWS];
    const int b  = blockIdx.y;
    const int s0 = blockIdx.x * ROWS;

    if (threadIdx.x < ROWS)
        xs[threadIdx.x] = __ldcg(g_zbuf + OFF_W2 + b * SS + s0 + threadIdx.x);
    __syncthreads();
    matvec_body(step + (size_t)b * SS * SS + (size_t)s0 * SS, xs, threadIdx.x * 4,
                g_zbuf + OFF_W3 + b * SS + threadIdx.x * 4);
}

// ---------------- map pass: wsum on the fly; accv += wsum_chunk @ map -------
// grid = (8, 64). Each CTA owns (b, s-chunk) exclusively -> writes wsum once.
__global__ void __launch_bounds__(256) k_mapC(
    const float* __restrict__ map, const float* __restrict__ step,
    const int* __restrict__ qidx, const float* __restrict__ qmask)
{
    __shared__ float xs[ROWS];
    const int b  = blockIdx.y;
    const int s0 = blockIdx.x * ROWS;
    const int q = qidx[b];
    const float m = qmask[b];

    if (threadIdx.x < ROWS) {
        int s = s0 + threadIdx.x;
        float v = m * __ldg(step + ((size_t)b * SS + (size_t)q) * SS + s)
                + __ldcg(g_zbuf + OFF_W2 + b * SS + s)
                + __ldcg(g_zbuf + OFF_W3 + b * SS + s);
        if (s == q) v += m;
        xs[threadIdx.x] = v;
        g_buf[OFF_WSUM + b * SS + s] = v;   // consumed by symbol_bank GEMM
    }
    __syncthreads();
    matvec_body(map + (size_t)b * SS * SS + (size_t)s0 * SS, xs, threadIdx.x * 4,
                g_zbuf + OFF_ACCV + b * SS + threadIdx.x * 4);
}

// ---------------- gelu ----------------
__device__ __forceinline__ float gelu_tanh(float x) {
    float x3 = x * x * x;
    return 0.5f * x * (1.0f + tanhf(0.7978845608028654f * (x + 0.044715f * x3)));
}

// ---------------- split-K GEMM with z-paired operands ----------------
// C[64, 1024-per-z] += act(A[64,Ktot]) @ W[Ktot,1024]  (atomic accumulate)
// grid = (16 n-blocks, KSPLIT, 2), block = 256. BM=64 BN=64 BK=16, 4x4/thread.
// AGELU=1: apply gelu(a + biasA[k]) to A elements at load time.
template <int KSPLIT, int AGELU>
__global__ void __launch_bounds__(256) k_gemm(
    const float* __restrict__ A0, const float* __restrict__ A1,
    const float* __restrict__ bA0, const float* __restrict__ bA1,
    const float* __restrict__ W0, const float* __restrict__ W1,
    float* __restrict__ C0, float* __restrict__ C1,
    int lda, int ldc, int Ktot)
{
    const float* A  = blockIdx.z ? A1  : A0;
    const float* Ab = blockIdx.z ? bA1 : bA0;
    const float* W  = blockIdx.z ? W1  : W0;
    float*       C  = blockIdx.z ? C1  : C0;

    const int n0 = blockIdx.x * 64;
    const int kchunk = Ktot / KSPLIT;
    const int k0 = blockIdx.y * kchunk;

    __shared__ float As[16][68];
    __shared__ float Ws[16][64];

    const int tid = threadIdx.x;
    const int tx = tid & 15;
    const int ty = tid >> 4;

    float acc[4][4] = {};

    const int lm = tid >> 2;
    const int lk = (tid & 3) * 4;
    const int wk = tid >> 4;
    const int wn = (tid & 15) * 4;

    for (int kt = k0; kt < k0 + kchunk; kt += 16) {
        float4 a = *reinterpret_cast<const float4*>(A + (size_t)lm * lda + kt + lk);
        if (AGELU) {
            const float* bp = Ab + kt + lk;
            a.x = gelu_tanh(a.x + bp[0]);
            a.y = gelu_tanh(a.y + bp[1]);
            a.z = gelu_tanh(a.z + bp[2]);
            a.w = gelu_tanh(a.w + bp[3]);
        }
        As[lk + 0][lm] = a.x;
        As[lk + 1][lm] = a.y;
        As[lk + 2][lm] = a.z;
        As[lk + 3][lm] = a.w;
        *reinterpret_cast<float4*>(&Ws[wk][wn]) =
            *reinterpret_cast<const float4*>(W + (size_t)(kt + wk) * 1024 + n0 + wn);
        __syncthreads();
#pragma unroll
        for (int k = 0; k < 16; ++k) {
            float4 av = *reinterpret_cast<const float4*>(&As[k][ty * 4]);
            float4 bv = *reinterpret_cast<const float4*>(&Ws[k][tx * 4]);
            acc[0][0] += av.x * bv.x; acc[0][1] += av.x * bv.y;
            acc[0][2] += av.x * bv.z; acc[0][3] += av.x * bv.w;
            acc[1][0] += av.y * bv.x; acc[1][1] += av.y * bv.y;
            acc[1][2] += av.y * bv.z; acc[1][3] += av.y * bv.w;
            acc[2][0] += av.z * bv.x; acc[2][1] += av.z * bv.y;
            acc[2][2] += av.z * bv.z; acc[2][3] += av.z * bv.w;
            acc[3][0] += av.w * bv.x; acc[3][1] += av.w * bv.y;
            acc[3][2] += av.w * bv.z; acc[3][3] += av.w * bv.w;
        }
        __syncthreads();
    }

#pragma unroll
    for (int i = 0; i < 4; ++i) {
        int m = ty * 4 + i;
#pragma unroll
        for (int j = 0; j < 4; ++j) {
            int n = n0 + tx * 4 + j;
            atomicAdd(&C[(size_t)m * ldc + n], acc[i][j]);
        }
    }
}

// ---------------- out pre-init with final biases ----------------
__global__ void k_outinit(float* __restrict__ out,
                          const float* __restrict__ bo2,
                          const float* __restrict__ bf2) {
    int i = blockIdx.x * blockDim.x + threadIdx.x;   // 0..32767 float4s
    int e0 = i * 4;
    int n = e0 & 1023;
    const float* bp = (e0 < BB * VV) ? (bo2 + n) : (bf2 + n);
    *reinterpret_cast<float4*>(out + e0) = *reinterpret_cast<const float4*>(bp);
}

// ---------------- launch ----------------
extern "C" void kernel_launch(void* const* d_in, const int* in_sizes, int n_in,
                              void* d_out, int out_size) {
    const float* map_memory  = (const float*)d_in[0];
    const float* step_memory = (const float*)d_in[1];
    const int*   query_idx   = (const int*)  d_in[2];
    const float* query_mask  = (const float*)d_in[3];
    const float* symbol_bank = (const float*)d_in[4];
    const float* value_bank  = (const float*)d_in[5];
    const float* Wo1 = (const float*)d_in[6];
    const float* bo1 = (const float*)d_in[7];
    const float* Wo2 = (const float*)d_in[8];
    const float* bo2 = (const float*)d_in[9];
    const float* Wf1 = (const float*)d_in[10];
    const float* bf1 = (const float*)d_in[11];
    const float* Wf2 = (const float*)d_in[12];
    const float* bf2 = (const float*)d_in[13];
    float* out = (float*)d_out;

    float *zbuf, *buf;
    cudaGetSymbolAddress((void**)&zbuf, g_zbuf);
    cudaGetSymbolAddress((void**)&buf,  g_buf);

    float* pwsum = buf  + OFF_WSUM;
    float* paccv = zbuf + OFF_ACCV;
    float* pgs   = zbuf + OFF_GS;
    float* phpre = zbuf + OFF_HPRE;

    // zero all atomic-accumulation targets; pre-bias d_out
    cudaMemsetAsync(zbuf, 0, (BB * SS * 4 + BB * 2048) * sizeof(float));
    k_outinit<<<128, 256>>>(out, bo2, bf2);

    // walk: 512-CTA passes (8 s-chunks x 64 batches), 8-deep load batching
    dim3 mg(SS / ROWS, BB);
    k_stepA<<<mg, 256>>>(step_memory, query_idx, query_mask);   // w2
    k_stepB<<<mg, 256>>>(step_memory);                          // w3
    k_mapC <<<mg, 256>>>(map_memory, step_memory, query_idx, query_mask); // wsum+accv

    // gs = wsum@symbol_bank + accv@value_bank   (z-paired, both into pgs)
    dim3 gg(16, 16, 2);
    k_gemm<16, 0><<<gg, 256>>>(pwsum, paccv, nullptr, nullptr,
                               symbol_bank, value_bank, pgs, pgs, SS, DD, SS);
    // hpre = [gs@Wo1 | gs@Wf1]
    k_gemm<16, 0><<<gg, 256>>>(pgs, pgs, nullptr, nullptr,
                               Wo1, Wf1, phpre, phpre + 1024, DD, 2048, DD);
    // out += [gelu(hpre_o+bo1)@Wo2 | gelu(hpre_f+bf1)@Wf2]  (gelu fused in A-load)
    k_gemm<16, 1><<<gg, 256>>>(phpre, phpre + 1024, bo1, bf1,
                               Wo2, Wf2, out, out + BB * VV, 2048, 1024, DD);
}

// round 11
// speedup vs baseline: 1.0848x; 1.0234x over previous
#include <cuda_runtime.h>

#define BB 64
#define SS 1024
#define DD 1024
#define VV 1024

typedef unsigned long long ull;

// ---------------- scratch (no allocation allowed) ----------------
// zeroed-every-call region (one contiguous memset):
//   [0]      w2    (64K floats)
//   [64K]    w3    (64K)
//   [128K]   accv  (64K)
//   [192K]   gs    (64K)
//   [256K]   hpre  (128K) -> [64][2048] (ho_pre | hf_pre)
__device__ float g_zbuf[BB * SS * 4 + BB * 2048];
// non-zeroed scratch: wsum (64K)
__device__ float g_buf[BB * SS];

#define OFF_W2   0
#define OFF_W3   (BB * SS)
#define OFF_ACCV (BB * SS * 2)
#define OFF_GS   (BB * SS * 3)
#define OFF_HPRE (BB * SS * 4)

#define OFF_WSUM 0

#define ROWS 128           // s-rows per CTA per pass (grid = 8 x 64 = 512 CTAs)

// ---- f32x2 packed helpers (FFMA2 exists on sm_103a only via PTX) ----
__device__ __forceinline__ ull pack_bcast(float x) {
    ull r;
    asm("mov.b64 %0, {%1, %1};" : "=l"(r) : "r"(__float_as_uint(x)));
    return r;
}
__device__ __forceinline__ ull fma2(ull a, ull b, ull c) {
    ull r;
    asm("fma.rn.f32x2 %0, %1, %2, %3;" : "=l"(r) : "l"(a), "l"(b), "l"(c));
    return r;
}
__device__ __forceinline__ float2 unpack2(ull v) {
    unsigned lo, hi;
    asm("mov.b64 {%0, %1}, %2;" : "=r"(lo), "=r"(hi) : "l"(v));
    return make_float2(__uint_as_float(lo), __uint_as_float(hi));
}

// ---- shared inner loop: ROWS rows x 1024 cols, 8-deep manual load batching -
__device__ __forceinline__ void matvec_body(
    const float* __restrict__ Mb, const float* xs, int t0, float* __restrict__ y)
{
    float a0 = 0.f, a1 = 0.f, a2 = 0.f, a3 = 0.f;
#pragma unroll 1
    for (int s = 0; s < ROWS; s += 8) {
        float4 m[8];
#pragma unroll
        for (int j = 0; j < 8; ++j)
            m[j] = __ldcs(reinterpret_cast<const float4*>(Mb + (size_t)(s + j) * SS + t0));
#pragma unroll
        for (int j = 0; j < 8; ++j) {
            float x = xs[s + j];
            a0 += x * m[j].x; a1 += x * m[j].y;
            a2 += x * m[j].z; a3 += x * m[j].w;
        }
    }
    atomicAdd(y + 0, a0); atomicAdd(y + 1, a1);
    atomicAdd(y + 2, a2); atomicAdd(y + 3, a3);
}

// ---------------- step pass A: w2[b,:] += w1_chunk @ step[b] ----------------
__global__ void __launch_bounds__(256) k_stepA(
    const float* __restrict__ step,
    const int* __restrict__ qidx, const float* __restrict__ qmask)
{
    __shared__ float xs[ROWS];
    const int b  = blockIdx.y;
    const int s0 = blockIdx.x * ROWS;
    const float* stepb = step + (size_t)b * SS * SS;

    if (threadIdx.x < ROWS) {
        int q = qidx[b];
        xs[threadIdx.x] = qmask[b] * __ldg(stepb + (size_t)q * SS + s0 + threadIdx.x);
    }
    __syncthreads();
    matvec_body(stepb + (size_t)s0 * SS, xs, threadIdx.x * 4,
                g_zbuf + OFF_W2 + b * SS + threadIdx.x * 4);
}

// ---------------- step pass B: w3[b,:] += w2_chunk @ step[b] ----------------
__global__ void __launch_bounds__(256) k_stepB(const float* __restrict__ step)
{
    __shared__ float xs[ROWS];
    const int b  = blockIdx.y;
    const int s0 = blockIdx.x * ROWS;

    if (threadIdx.x < ROWS)
        xs[threadIdx.x] = __ldcg(g_zbuf + OFF_W2 + b * SS + s0 + threadIdx.x);
    __syncthreads();
    matvec_body(step + (size_t)b * SS * SS + (size_t)s0 * SS, xs, threadIdx.x * 4,
                g_zbuf + OFF_W3 + b * SS + threadIdx.x * 4);
}

// ---------------- map pass: wsum on the fly; accv += wsum_chunk @ map -------
__global__ void __launch_bounds__(256) k_mapC(
    const float* __restrict__ map, const float* __restrict__ step,
    const int* __restrict__ qidx, const float* __restrict__ qmask)
{
    __shared__ float xs[ROWS];
    const int b  = blockIdx.y;
    const int s0 = blockIdx.x * ROWS;
    const int q = qidx[b];
    const float m = qmask[b];

    if (threadIdx.x < ROWS) {
        int s = s0 + threadIdx.x;
        float v = m * __ldg(step + ((size_t)b * SS + (size_t)q) * SS + s)
                + __ldcg(g_zbuf + OFF_W2 + b * SS + s)
                + __ldcg(g_zbuf + OFF_W3 + b * SS + s);
        if (s == q) v += m;
        xs[threadIdx.x] = v;
        g_buf[OFF_WSUM + b * SS + s] = v;   // consumed by symbol_bank GEMM
    }
    __syncthreads();
    matvec_body(map + (size_t)b * SS * SS + (size_t)s0 * SS, xs, threadIdx.x * 4,
                g_zbuf + OFF_ACCV + b * SS + threadIdx.x * 4);
}

// ---------------- gelu ----------------
__device__ __forceinline__ float gelu_tanh(float x) {
    float x3 = x * x * x;
    return 0.5f * x * (1.0f + tanhf(0.7978845608028654f * (x + 0.044715f * x3)));
}

// ---------------- split-K GEMM, f32x2 packed micro-kernel ----------------
// C[64, 1024-per-z] += act(A[64,Ktot]) @ W[Ktot,1024]  (atomic accumulate)
// grid = (16 n-blocks, KSPLIT, 2), block = 256. BM=64 BN=64 BK=16, 4x4/thread.
template <int KSPLIT, int AGELU>
__global__ void __launch_bounds__(256) k_gemm(
    const float* __restrict__ A0, const float* __restrict__ A1,
    const float* __restrict__ bA0, const float* __restrict__ bA1,
    const float* __restrict__ W0, const float* __restrict__ W1,
    float* __restrict__ C0, float* __restrict__ C1,
    int lda, int ldc, int Ktot)
{
    const float* A  = blockIdx.z ? A1  : A0;
    const float* Ab = blockIdx.z ? bA1 : bA0;
    const float* W  = blockIdx.z ? W1  : W0;
    float*       C  = blockIdx.z ? C1  : C0;

    const int n0 = blockIdx.x * 64;
    const int kchunk = Ktot / KSPLIT;
    const int k0 = blockIdx.y * kchunk;

    __shared__ float As[16][68];
    __shared__ float Ws[16][64];

    const int tid = threadIdx.x;
    const int tx = tid & 15;
    const int ty = tid >> 4;

    // acc2[i][p] = packed pair (n = tx*4 + 2p, tx*4 + 2p + 1) for row ty*4+i
    ull acc2[4][2] = {};

    const int lm = tid >> 2;
    const int lk = (tid & 3) * 4;
    const int wk = tid >> 4;
    const int wn = (tid & 15) * 4;

    for (int kt = k0; kt < k0 + kchunk; kt += 16) {
        float4 a = *reinterpret_cast<const float4*>(A + (size_t)lm * lda + kt + lk);
        if (AGELU) {
            const float* bp = Ab + kt + lk;
            a.x = gelu_tanh(a.x + bp[0]);
            a.y = gelu_tanh(a.y + bp[1]);
            a.z = gelu_tanh(a.z + bp[2]);
            a.w = gelu_tanh(a.w + bp[3]);
        }
        As[lk + 0][lm] = a.x;
        As[lk + 1][lm] = a.y;
        As[lk + 2][lm] = a.z;
        As[lk + 3][lm] = a.w;
        *reinterpret_cast<float4*>(&Ws[wk][wn]) =
            *reinterpret_cast<const float4*>(W + (size_t)(kt + wk) * 1024 + n0 + wn);
        __syncthreads();
#pragma unroll
        for (int k = 0; k < 16; ++k) {
            float4 av = *reinterpret_cast<const float4*>(&As[k][ty * 4]);
            const ull* bp = reinterpret_cast<const ull*>(&Ws[k][tx * 4]);
            ull b01 = bp[0];
            ull b23 = bp[1];
            ull ax = pack_bcast(av.x);
            ull ay = pack_bcast(av.y);
            ull az = pack_bcast(av.z);
            ull aw = pack_bcast(av.w);
            acc2[0][0] = fma2(ax, b01, acc2[0][0]);
            acc2[0][1] = fma2(ax, b23, acc2[0][1]);
            acc2[1][0] = fma2(ay, b01, acc2[1][0]);
            acc2[1][1] = fma2(ay, b23, acc2[1][1]);
            acc2[2][0] = fma2(az, b01, acc2[2][0]);
            acc2[2][1] = fma2(az, b23, acc2[2][1]);
            acc2[3][0] = fma2(aw, b01, acc2[3][0]);
            acc2[3][1] = fma2(aw, b23, acc2[3][1]);
        }
        __syncthreads();
    }

#pragma unroll
    for (int i = 0; i < 4; ++i) {
        int m = ty * 4 + i;
        float2 p0 = unpack2(acc2[i][0]);
        float2 p1 = unpack2(acc2[i][1]);
        float* cp = &C[(size_t)m * ldc + n0 + tx * 4];
        atomicAdd(cp + 0, p0.x);
        atomicAdd(cp + 1, p0.y);
        atomicAdd(cp + 2, p1.x);
        atomicAdd(cp + 3, p1.y);
    }
}

// ---------------- out pre-init with final biases ----------------
__global__ void k_outinit(float* __restrict__ out,
                          const float* __restrict__ bo2,
                          const float* __restrict__ bf2) {
    int i = blockIdx.x * blockDim.x + threadIdx.x;   // 0..32767 float4s
    int e0 = i * 4;
    int n = e0 & 1023;
    const float* bp = (e0 < BB * VV) ? (bo2 + n) : (bf2 + n);
    *reinterpret_cast<float4*>(out + e0) = *reinterpret_cast<const float4*>(bp);
}

// ---------------- launch ----------------
extern "C" void kernel_launch(void* const* d_in, const int* in_sizes, int n_in,
                              void* d_out, int out_size) {
    const float* map_memory  = (const float*)d_in[0];
    const float* step_memory = (const float*)d_in[1];
    const int*   query_idx   = (const int*)  d_in[2];
    const float* query_mask  = (const float*)d_in[3];
    const float* symbol_bank = (const float*)d_in[4];
    const float* value_bank  = (const float*)d_in[5];
    const float* Wo1 = (const float*)d_in[6];
    const float* bo1 = (const float*)d_in[7];
    const float* Wo2 = (const float*)d_in[8];
    const float* bo2 = (const float*)d_in[9];
    const float* Wf1 = (const float*)d_in[10];
    const float* bf1 = (const float*)d_in[11];
    const float* Wf2 = (const float*)d_in[12];
    const float* bf2 = (const float*)d_in[13];
    float* out = (float*)d_out;

    float *zbuf, *buf;
    cudaGetSymbolAddress((void**)&zbuf, g_zbuf);
    cudaGetSymbolAddress((void**)&buf,  g_buf);

    float* pwsum = buf  + OFF_WSUM;
    float* paccv = zbuf + OFF_ACCV;
    float* pgs   = zbuf + OFF_GS;
    float* phpre = zbuf + OFF_HPRE;

    // zero all atomic-accumulation targets; pre-bias d_out
    cudaMemsetAsync(zbuf, 0, (BB * SS * 4 + BB * 2048) * sizeof(float));
    k_outinit<<<128, 256>>>(out, bo2, bf2);

    // walk: 512-CTA passes (8 s-chunks x 64 batches), 8-deep load batching
    dim3 mg(SS / ROWS, BB);
    k_stepA<<<mg, 256>>>(step_memory, query_idx, query_mask);   // w2
    k_stepB<<<mg, 256>>>(step_memory);                          // w3
    k_mapC <<<mg, 256>>>(map_memory, step_memory, query_idx, query_mask); // wsum+accv

    // gs = wsum@symbol_bank + accv@value_bank   (z-paired, both into pgs)
    dim3 gg(16, 16, 2);
    k_gemm<16, 0><<<gg, 256>>>(pwsum, paccv, nullptr, nullptr,
                               symbol_bank, value_bank, pgs, pgs, SS, DD, SS);
    // hpre = [gs@Wo1 | gs@Wf1]
    k_gemm<16, 0><<<gg, 256>>>(pgs, pgs, nullptr, nullptr,
                               Wo1, Wf1, phpre, phpre + 1024, DD, 2048, DD);
    // out += [gelu(hpre_o+bo1)@Wo2 | gelu(hpre_f+bf1)@Wf2]  (gelu fused in A-load)
    k_gemm<16, 1><<<gg, 256>>>(phpre, phpre + 1024, bo1, bf1,
                               Wo2, Wf2, out, out + BB * VV, 2048, 1024, DD);
}

// round 12
// speedup vs baseline: 1.1058x; 1.0194x over previous
#include <cuda_runtime.h>

#define BB 64
#define SS 1024
#define DD 1024
#define VV 1024

typedef unsigned long long ull;

// ---------------- scratch (no allocation allowed) ----------------
// zeroed-every-call region (zeroed by k_init):
//   [0]      w2    (64K floats)
//   [64K]    w3    (64K)
//   [128K]   accv  (64K)
//   [192K]   gs    (64K)
//   [256K]   hpre  (128K) -> [64][2048] (ho_pre | hf_pre)
__device__ float g_zbuf[BB * SS * 4 + BB * 2048];
// non-zeroed scratch: wsum (64K)
__device__ float g_buf[BB * SS];

#define OFF_W2   0
#define OFF_W3   (BB * SS)
#define OFF_ACCV (BB * SS * 2)
#define OFF_GS   (BB * SS * 3)
#define OFF_HPRE (BB * SS * 4)
#define NZ       (BB * SS * 4 + BB * 2048)   // 393216 floats to zero

#define OFF_WSUM 0

#define ROWS 128           // s-rows per CTA per pass (grid = 8 x 64 = 512 CTAs)

// ---- f32x2 packed helpers (FFMA2 exists on sm_103a only via PTX) ----
__device__ __forceinline__ ull pack_bcast(float x) {
    ull r;
    asm("mov.b64 %0, {%1, %1};" : "=l"(r) : "r"(__float_as_uint(x)));
    return r;
}
__device__ __forceinline__ ull fma2(ull a, ull b, ull c) {
    ull r;
    asm("fma.rn.f32x2 %0, %1, %2, %3;" : "=l"(r) : "l"(a), "l"(b), "l"(c));
    return r;
}
__device__ __forceinline__ float2 unpack2(ull v) {
    unsigned lo, hi;
    asm("mov.b64 {%0, %1}, %2;" : "=r"(lo), "=r"(hi) : "l"(v));
    return make_float2(__uint_as_float(lo), __uint_as_float(hi));
}

// ---- shared inner loop: ROWS rows x 1024 cols, 8-deep manual load batching -
__device__ __forceinline__ void matvec_body(
    const float* __restrict__ Mb, const float* xs, int t0, float* __restrict__ y)
{
    float a0 = 0.f, a1 = 0.f, a2 = 0.f, a3 = 0.f;
#pragma unroll 1
    for (int s = 0; s < ROWS; s += 8) {
        float4 m[8];
#pragma unroll
        for (int j = 0; j < 8; ++j)
            m[j] = __ldcs(reinterpret_cast<const float4*>(Mb + (size_t)(s + j) * SS + t0));
#pragma unroll
        for (int j = 0; j < 8; ++j) {
            float x = xs[s + j];
            a0 += x * m[j].x; a1 += x * m[j].y;
            a2 += x * m[j].z; a3 += x * m[j].w;
        }
    }
    atomicAdd(y + 0, a0); atomicAdd(y + 1, a1);
    atomicAdd(y + 2, a2); atomicAdd(y + 3, a3);
}

// ---------------- step pass A: w2[b,:] += w1_chunk @ step[b] ----------------
__global__ void __launch_bounds__(256) k_stepA(
    const float* __restrict__ step,
    const int* __restrict__ qidx, const float* __restrict__ qmask)
{
    __shared__ float xs[ROWS];
    const int b  = blockIdx.y;
    const int s0 = blockIdx.x * ROWS;
    const float* stepb = step + (size_t)b * SS * SS;

    if (threadIdx.x < ROWS) {
        int q = qidx[b];
        xs[threadIdx.x] = qmask[b] * __ldg(stepb + (size_t)q * SS + s0 + threadIdx.x);
    }
    __syncthreads();
    matvec_body(stepb + (size_t)s0 * SS, xs, threadIdx.x * 4,
                g_zbuf + OFF_W2 + b * SS + threadIdx.x * 4);
}

// ---------------- step pass B: w3[b,:] += w2_chunk @ step[b] ----------------
__global__ void __launch_bounds__(256) k_stepB(const float* __restrict__ step)
{
    __shared__ float xs[ROWS];
    const int b  = blockIdx.y;
    const int s0 = blockIdx.x * ROWS;

    if (threadIdx.x < ROWS)
        xs[threadIdx.x] = __ldcg(g_zbuf + OFF_W2 + b * SS + s0 + threadIdx.x);
    __syncthreads();
    matvec_body(step + (size_t)b * SS * SS + (size_t)s0 * SS, xs, threadIdx.x * 4,
                g_zbuf + OFF_W3 + b * SS + threadIdx.x * 4);
}

// ---------------- map pass: wsum on the fly; accv += wsum_chunk @ map -------
__global__ void __launch_bounds__(256) k_mapC(
    const float* __restrict__ map, const float* __restrict__ step,
    const int* __restrict__ qidx, const float* __restrict__ qmask)
{
    __shared__ float xs[ROWS];
    const int b  = blockIdx.y;
    const int s0 = blockIdx.x * ROWS;
    const int q = qidx[b];
    const float m = qmask[b];

    if (threadIdx.x < ROWS) {
        int s = s0 + threadIdx.x;
        float v = m * __ldg(step + ((size_t)b * SS + (size_t)q) * SS + s)
                + __ldcg(g_zbuf + OFF_W2 + b * SS + s)
                + __ldcg(g_zbuf + OFF_W3 + b * SS + s);
        if (s == q) v += m;
        xs[threadIdx.x] = v;
        g_buf[OFF_WSUM + b * SS + s] = v;   // consumed by symbol_bank GEMM
    }
    __syncthreads();
    matvec_body(map + (size_t)b * SS * SS + (size_t)s0 * SS, xs, threadIdx.x * 4,
                g_zbuf + OFF_ACCV + b * SS + threadIdx.x * 4);
}

// ---------------- gelu ----------------
__device__ __forceinline__ float gelu_tanh(float x) {
    float x3 = x * x * x;
    return 0.5f * x * (1.0f + tanhf(0.7978845608028654f * (x + 0.044715f * x3)));
}

// ---------------- split-K GEMM, f32x2 packed, double-buffered ----------------
// C[64, 1024-per-z] += act(A[64,Ktot]) @ W[Ktot,1024]  (atomic accumulate)
// grid = (16 n-blocks, KSPLIT, 2), block = 256. BM=64 BN=64 BK=16, 4x4/thread.
template <int KSPLIT, int AGELU>
__global__ void __launch_bounds__(256) k_gemm(
    const float* __restrict__ A0, const float* __restrict__ A1,
    const float* __restrict__ bA0, const float* __restrict__ bA1,
    const float* __restrict__ W0, const float* __restrict__ W1,
    float* __restrict__ C0, float* __restrict__ C1,
    int lda, int ldc, int Ktot)
{
    const float* A  = blockIdx.z ? A1  : A0;
    const float* Ab = blockIdx.z ? bA1 : bA0;
    const float* W  = blockIdx.z ? W1  : W0;
    float*       C  = blockIdx.z ? C1  : C0;

    const int n0 = blockIdx.x * 64;
    const int kchunk = Ktot / KSPLIT;
    const int k0 = blockIdx.y * kchunk;
    const int T  = kchunk / 16;          // tiles per CTA

    __shared__ float As[2][16][68];
    __shared__ float Ws[2][16][64];

    const int tid = threadIdx.x;
    const int tx = tid & 15;
    const int ty = tid >> 4;

    ull acc2[4][2] = {};

    const int lm = tid >> 2;
    const int lk = (tid & 3) * 4;
    const int wk = tid >> 4;
    const int wn = (tid & 15) * 4;

    // prologue: load tile 0 into buffer 0
    {
        float4 a = *reinterpret_cast<const float4*>(A + (size_t)lm * lda + k0 + lk);
        if (AGELU) {
            const float* bp = Ab + k0 + lk;
            a.x = gelu_tanh(a.x + bp[0]);
            a.y = gelu_tanh(a.y + bp[1]);
            a.z = gelu_tanh(a.z + bp[2]);
            a.w = gelu_tanh(a.w + bp[3]);
        }
        As[0][lk + 0][lm] = a.x;
        As[0][lk + 1][lm] = a.y;
        As[0][lk + 2][lm] = a.z;
        As[0][lk + 3][lm] = a.w;
        *reinterpret_cast<float4*>(&Ws[0][wk][wn]) =
            *reinterpret_cast<const float4*>(W + (size_t)(k0 + wk) * 1024 + n0 + wn);
    }
    __syncthreads();

#pragma unroll 1
    for (int t = 0; t < T; ++t) {
        const int cur = t & 1;
        const int nxt = cur ^ 1;

        float4 a_n, w_n;
        if (t + 1 < T) {
            const int kt = k0 + (t + 1) * 16;
            a_n = *reinterpret_cast<const float4*>(A + (size_t)lm * lda + kt + lk);
            w_n = *reinterpret_cast<const float4*>(W + (size_t)(kt + wk) * 1024 + n0 + wn);
        }

#pragma unroll
        for (int k = 0; k < 16; ++k) {
            float4 av = *reinterpret_cast<const float4*>(&As[cur][k][ty * 4]);
            const ull* bp = reinterpret_cast<const ull*>(&Ws[cur][k][tx * 4]);
            ull b01 = bp[0];
            ull b23 = bp[1];
            ull ax = pack_bcast(av.x);
            ull ay = pack_bcast(av.y);
            ull az = pack_bcast(av.z);
            ull aw = pack_bcast(av.w);
            acc2[0][0] = fma2(ax, b01, acc2[0][0]);
            acc2[0][1] = fma2(ax, b23, acc2[0][1]);
            acc2[1][0] = fma2(ay, b01, acc2[1][0]);
            acc2[1][1] = fma2(ay, b23, acc2[1][1]);
            acc2[2][0] = fma2(az, b01, acc2[2][0]);
            acc2[2][1] = fma2(az, b23, acc2[2][1]);
            acc2[3][0] = fma2(aw, b01, acc2[3][0]);
            acc2[3][1] = fma2(aw, b23, acc2[3][1]);
        }

        if (t + 1 < T) {
            const int kt = k0 + (t + 1) * 16;
            if (AGELU) {
                const float* bp = Ab + kt + lk;
                a_n.x = gelu_tanh(a_n.x + bp[0]);
                a_n.y = gelu_tanh(a_n.y + bp[1]);
                a_n.z = gelu_tanh(a_n.z + bp[2]);
                a_n.w = gelu_tanh(a_n.w + bp[3]);
            }
            As[nxt][lk + 0][lm] = a_n.x;
            As[nxt][lk + 1][lm] = a_n.y;
            As[nxt][lk + 2][lm] = a_n.z;
            As[nxt][lk + 3][lm] = a_n.w;
            *reinterpret_cast<float4*>(&Ws[nxt][wk][wn]) = w_n;
            __syncthreads();
        }
    }

#pragma unroll
    for (int i = 0; i < 4; ++i) {
        int m = ty * 4 + i;
        float2 p0 = unpack2(acc2[i][0]);
        float2 p1 = unpack2(acc2[i][1]);
        float* cp = &C[(size_t)m * ldc + n0 + tx * 4];
        atomicAdd(cp + 0, p0.x);
        atomicAdd(cp + 1, p0.y);
        atomicAdd(cp + 2, p1.x);
        atomicAdd(cp + 3, p1.y);
    }
}

// ---------------- init: zero zbuf + pre-bias d_out (one kernel) ----------------
// grid = 512, block = 256: 131072 threads, one float4 each.
__global__ void k_init(float* __restrict__ out,
                       const float* __restrict__ bo2,
                       const float* __restrict__ bf2) {
    int i = blockIdx.x * blockDim.x + threadIdx.x;
    if (i < NZ / 4) {
        *reinterpret_cast<float4*>(g_zbuf + i * 4) = make_float4(0.f, 0.f, 0.f, 0.f);
    } else {
        int e0 = (i - NZ / 4) * 4;                  // 0 .. 131071
        int n = e0 & 1023;
        const float* bp = (e0 < BB * VV) ? (bo2 + n) : (bf2 + n);
        *reinterpret_cast<float4*>(out + e0) = *reinterpret_cast<const float4*>(bp);
    }
}

// ---------------- launch ----------------
extern "C" void kernel_launch(void* const* d_in, const int* in_sizes, int n_in,
                              void* d_out, int out_size) {
    const float* map_memory  = (const float*)d_in[0];
    const float* step_memory = (const float*)d_in[1];
    const int*   query_idx   = (const int*)  d_in[2];
    const float* query_mask  = (const float*)d_in[3];
    const float* symbol_bank = (const float*)d_in[4];
    const float* value_bank  = (const float*)d_in[5];
    const float* Wo1 = (const float*)d_in[6];
    const float* bo1 = (const float*)d_in[7];
    const float* Wo2 = (const float*)d_in[8];
    const float* bo2 = (const float*)d_in[9];
    const float* Wf1 = (const float*)d_in[10];
    const float* bf1 = (const float*)d_in[11];
    const float* Wf2 = (const float*)d_in[12];
    const float* bf2 = (const float*)d_in[13];
    float* out = (float*)d_out;

    float *zbuf, *buf;
    cudaGetSymbolAddress((void**)&zbuf, g_zbuf);
    cudaGetSymbolAddress((void**)&buf,  g_buf);

    float* pwsum = buf  + OFF_WSUM;
    float* paccv = zbuf + OFF_ACCV;
    float* pgs   = zbuf + OFF_GS;
    float* phpre = zbuf + OFF_HPRE;

    // zero accumulation targets + pre-bias d_out, one launch
    // threads needed: NZ/4 + 32768 = 98304 + 32768 = 131072 = 512*256
    k_init<<<512, 256>>>(out, bo2, bf2);

    // walk: 512-CTA passes (8 s-chunks x 64 batches), 8-deep load batching
    dim3 mg(SS / ROWS, BB);
    k_stepA<<<mg, 256>>>(step_memory, query_idx, query_mask);   // w2
    k_stepB<<<mg, 256>>>(step_memory);                          // w3
    k_mapC <<<mg, 256>>>(map_memory, step_memory, query_idx, query_mask); // wsum+accv

    // gs = wsum@symbol_bank + accv@value_bank   (z-paired, both into pgs)
    dim3 gg(16, 16, 2);
    k_gemm<16, 0><<<gg, 256>>>(pwsum, paccv, nullptr, nullptr,
                               symbol_bank, value_bank, pgs, pgs, SS, DD, SS);
    // hpre = [gs@Wo1 | gs@Wf1]
    k_gemm<16, 0><<<gg, 256>>>(pgs, pgs, nullptr, nullptr,
                               Wo1, Wf1, phpre, phpre + 1024, DD, 2048, DD);
    // out += [gelu(hpre_o+bo1)@Wo2 | gelu(hpre_f+bf1)@Wf2]  (gelu fused in A-load)
    k_gemm<16, 1><<<gg, 256>>>(phpre, phpre + 1024, bo1, bf1,
                               Wo2, Wf2, out, out + BB * VV, 2048, 1024, DD);
}